// round 4
// baseline (speedup 1.0000x reference)
#include <cuda_runtime.h>
#include <cstdint>

#define BB 16
#define CC 3
#define HH 1024
#define WW 1024
#define NFLAKES 15728

// 16 MB snow mask scratch (one byte per pixel per batch). __device__ global:
// allocation-free per harness rules.
__device__ unsigned char g_mask[(size_t)BB * HH * WW];

// ---------------------------------------------------------------------------
// Kernel 1: zero the mask (uint4 stores, 16 MB)
// ---------------------------------------------------------------------------
__global__ void zero_mask_kernel() {
    size_t i = (size_t)blockIdx.x * blockDim.x + threadIdx.x;
    reinterpret_cast<uint4*>(g_mask)[i] = make_uint4(0u, 0u, 0u, 0u);
}

// ---------------------------------------------------------------------------
// Kernel 2: stamp flakes. One thread per (b, flake). All writes are the
// constant 1, so write races / duplicate border-clamped writes are benign
// (matches the reference's constant 0.95 stamping semantics exactly).
// ---------------------------------------------------------------------------
__global__ void stamp_kernel(const int* __restrict__ ys,
                             const int* __restrict__ xs,
                             const int* __restrict__ rs) {
    int i = blockIdx.x * blockDim.x + threadIdx.x;
    if (i >= BB * NFLAKES) return;
    int b = i / NFLAKES;
    int y = ys[i];
    int x = xs[i];
    int r = rs[i];  // in {1,2,3}
    unsigned char* m = g_mask + (size_t)b * (HH * WW);
    for (int dy = -r; dy <= r; ++dy) {
        int yy = min(max(y + dy, 0), HH - 1);
        unsigned char* row = m + yy * WW;
        for (int dx = -r; dx <= r; ++dx) {
            int xx = min(max(x + dx, 0), WW - 1);
            row[xx] = 1;
        }
    }
}

// ---------------------------------------------------------------------------
// Kernel 3: fused (mask ? 0.95 : x) + separable 5x5 Gaussian + clip.
// Tile 32x32 outputs per block with a 2-pixel halo, 256 threads (32x8).
// ---------------------------------------------------------------------------
// Gaussian weights for sigma=1.5, K=5 (computed in double, hardcoded):
// g = exp(-k^2/4.5)/sum, k=-2..2
#define G0 0.1200785f   /* |k|=2 */
#define G1 0.2338807f   /* |k|=1 */
#define G2 0.2920817f   /* k=0   */

#define TS 32
#define HALO 2
#define SW (TS + 2 * HALO)   /* 36 */

__global__ __launch_bounds__(256) void blur_kernel(const float* __restrict__ x,
                                                   float* __restrict__ out) {
    __shared__ float s[SW][SW];     // raw (mask-substituted) values + halo
    __shared__ float hb[SW][TS];    // horizontally filtered

    const int bc = blockIdx.z;       // b*C + c
    const int b = bc / CC;
    const size_t plane = (size_t)bc * (HH * WW);
    const float* xp = x + plane;
    const unsigned char* mp = g_mask + (size_t)b * (HH * WW);

    const int tx0 = blockIdx.x * TS;
    const int ty0 = blockIdx.y * TS;
    const int tid = threadIdx.y * 32 + threadIdx.x;

    // Cooperative load of 36x36 tile (zero-padded at image borders),
    // fusing the snow-mask substitution.
    for (int idx = tid; idx < SW * SW; idx += 256) {
        int ly = idx / SW;
        int lx = idx - ly * SW;
        int gy = ty0 + ly - HALO;
        int gx = tx0 + lx - HALO;
        float v = 0.0f;
        if ((unsigned)gy < (unsigned)HH && (unsigned)gx < (unsigned)WW) {
            int o = gy * WW + gx;
            v = mp[o] ? 0.95f : xp[o];
        }
        s[ly][lx] = v;
    }
    __syncthreads();

    // Horizontal pass: 36 rows x 32 output columns.
    for (int idx = tid; idx < SW * TS; idx += 256) {
        int ly = idx / TS;
        int lx = idx - ly * TS;
        float a = G0 * (s[ly][lx] + s[ly][lx + 4])
                + G1 * (s[ly][lx + 1] + s[ly][lx + 3])
                + G2 * s[ly][lx + 2];
        hb[ly][lx] = a;
    }
    __syncthreads();

    // Vertical pass + clip + store: each thread produces 4 rows.
    const int lx = threadIdx.x;
#pragma unroll
    for (int k = 0; k < TS / 8; ++k) {
        int ly = threadIdx.y + k * 8;
        float a = G0 * (hb[ly][lx] + hb[ly + 4][lx])
                + G1 * (hb[ly + 1][lx] + hb[ly + 3][lx])
                + G2 * hb[ly + 2][lx];
        a = fminf(fmaxf(a, 0.0f), 1.0f);
        out[plane + (size_t)(ty0 + ly) * WW + (tx0 + lx)] = a;
    }
}

// ---------------------------------------------------------------------------
// Launch
// ---------------------------------------------------------------------------
extern "C" void kernel_launch(void* const* d_in, const int* in_sizes, int n_in,
                              void* d_out, int out_size) {
    const float* x  = (const float*)d_in[0];
    const int*   ys = (const int*)d_in[1];
    const int*   xs = (const int*)d_in[2];
    const int*   rs = (const int*)d_in[3];
    float* out = (float*)d_out;

    // 1) zero mask: B*H*W/16 uint4 elements
    {
        int n = (BB * HH * WW) / 16;            // 1,048,576
        zero_mask_kernel<<<n / 256, 256>>>();
    }
    // 2) stamp flakes
    {
        int n = BB * NFLAKES;                   // 251,648
        stamp_kernel<<<(n + 255) / 256, 256>>>(ys, xs, rs);
    }
    // 3) fused substitute + separable blur + clip
    {
        dim3 grid(WW / TS, HH / TS, BB * CC);   // 32 x 32 x 48
        dim3 block(32, 8);
        blur_kernel<<<grid, block>>>(x, out);
    }
}

// round 5
// speedup vs baseline: 1.6660x; 1.6660x over previous
#include <cuda_runtime.h>
#include <cstdint>

#define BB 16
#define CC 3
#define HH 1024
#define WW 1024
#define NFLAKES 15728

// 16 MB snow mask scratch (one byte per pixel per batch). __device__ global:
// allocation-free per harness rules.
__device__ unsigned char g_mask[(size_t)BB * HH * WW];

// ---------------------------------------------------------------------------
// Kernel 1: zero the mask (uint4 stores, 16 MB)
// ---------------------------------------------------------------------------
__global__ void zero_mask_kernel() {
    size_t i = (size_t)blockIdx.x * blockDim.x + threadIdx.x;
    reinterpret_cast<uint4*>(g_mask)[i] = make_uint4(0u, 0u, 0u, 0u);
}

// ---------------------------------------------------------------------------
// Kernel 2: stamp flakes. One thread per (b, flake). All writes are the
// constant 1, so write races / duplicate border-clamped writes are benign.
// ---------------------------------------------------------------------------
__global__ void stamp_kernel(const int* __restrict__ ys,
                             const int* __restrict__ xs,
                             const int* __restrict__ rs) {
    int i = blockIdx.x * blockDim.x + threadIdx.x;
    if (i >= BB * NFLAKES) return;
    int b = i / NFLAKES;
    int y = ys[i];
    int x = xs[i];
    int r = rs[i];  // in {1,2,3}
    unsigned char* m = g_mask + (size_t)b * (HH * WW);
    for (int dy = -r; dy <= r; ++dy) {
        int yy = min(max(y + dy, 0), HH - 1);
        unsigned char* row = m + yy * WW;
        for (int dx = -r; dx <= r; ++dx) {
            int xx = min(max(x + dx, 0), WW - 1);
            row[xx] = 1;
        }
    }
}

// ---------------------------------------------------------------------------
// Kernel 3: register sliding-window separable blur (no shared memory).
// Warp strip: 128 columns wide (lane = 4 consecutive cols, float4),
// 32 output rows tall. 5 horizontally-blurred rows live in registers.
// ---------------------------------------------------------------------------
// Gaussian weights for sigma=1.5, K=5: g = exp(-k^2/4.5)/sum
#define G0 0.1200785f   /* |k|=2 */
#define G1 0.2338807f   /* |k|=1 */
#define G2 0.2920817f   /* k=0   */

#define ROWS_PER_WARP 32
#define WARPS_PER_BLOCK 8

// Compute the horizontally-blurred 4-wide output for row gy, columns gx..gx+3,
// fusing snow-mask substitution and zero padding.
__device__ __forceinline__ float4 hrow_compute(const float* __restrict__ xp,
                                               const unsigned char* __restrict__ mp,
                                               int gy, int gx, bool okL, bool okR) {
    if ((unsigned)gy >= (unsigned)HH)
        return make_float4(0.f, 0.f, 0.f, 0.f);
    const float* row = xp + (size_t)gy * WW;
    const unsigned char* mr = mp + (size_t)gy * WW;

    float v[12];
    float4 f;
    unsigned m;

    // group 0: columns gx-4 .. gx-1 (fully in-range or fully out; strips aligned)
    if (okL) {
        f = *reinterpret_cast<const float4*>(row + gx - 4);
        m = *reinterpret_cast<const unsigned*>(mr + gx - 4);
    } else {
        f = make_float4(0.f, 0.f, 0.f, 0.f);
        m = 0u;
    }
    v[0] = (m & 0x000000FFu) ? 0.95f : f.x;
    v[1] = (m & 0x0000FF00u) ? 0.95f : f.y;
    v[2] = (m & 0x00FF0000u) ? 0.95f : f.z;
    v[3] = (m & 0xFF000000u) ? 0.95f : f.w;

    // group 1: columns gx .. gx+3 (always in range)
    f = *reinterpret_cast<const float4*>(row + gx);
    m = *reinterpret_cast<const unsigned*>(mr + gx);
    v[4] = (m & 0x000000FFu) ? 0.95f : f.x;
    v[5] = (m & 0x0000FF00u) ? 0.95f : f.y;
    v[6] = (m & 0x00FF0000u) ? 0.95f : f.z;
    v[7] = (m & 0xFF000000u) ? 0.95f : f.w;

    // group 2: columns gx+4 .. gx+7
    if (okR) {
        f = *reinterpret_cast<const float4*>(row + gx + 4);
        m = *reinterpret_cast<const unsigned*>(mr + gx + 4);
    } else {
        f = make_float4(0.f, 0.f, 0.f, 0.f);
        m = 0u;
    }
    v[8]  = (m & 0x000000FFu) ? 0.95f : f.x;
    v[9]  = (m & 0x0000FF00u) ? 0.95f : f.y;
    v[10] = (m & 0x00FF0000u) ? 0.95f : f.z;
    v[11] = (m & 0xFF000000u) ? 0.95f : f.w;

    // horizontal 5-tap: output i uses v[i+2 .. i+6]
    float4 o;
    o.x = G0 * (v[2] + v[6]) + G1 * (v[3] + v[5]) + G2 * v[4];
    o.y = G0 * (v[3] + v[7]) + G1 * (v[4] + v[6]) + G2 * v[5];
    o.z = G0 * (v[4] + v[8]) + G1 * (v[5] + v[7]) + G2 * v[6];
    o.w = G0 * (v[5] + v[9]) + G1 * (v[6] + v[8]) + G2 * v[7];
    return o;
}

__global__ __launch_bounds__(256) void blur_kernel(const float* __restrict__ x,
                                                   float* __restrict__ out) {
    const int bc = blockIdx.z;               // b*C + c
    const int b = bc / CC;
    const size_t plane = (size_t)bc * (HH * WW);
    const float* xp = x + plane;
    const unsigned char* mp = g_mask + (size_t)b * (HH * WW);
    float* op = out + plane;

    const int lane = threadIdx.x & 31;
    const int warp = threadIdx.x >> 5;
    const int gx = blockIdx.x * 128 + lane * 4;                       // column base
    const int y0 = (blockIdx.y * WARPS_PER_BLOCK + warp) * ROWS_PER_WARP;  // first output row

    const bool okL = (gx >= 4);
    const bool okR = (gx + 8 <= WW);

    // prologue: horizontally-blurred rows y0-2 .. y0+1
    float4 h0 = hrow_compute(xp, mp, y0 - 2, gx, okL, okR);
    float4 h1 = hrow_compute(xp, mp, y0 - 1, gx, okL, okR);
    float4 h2 = hrow_compute(xp, mp, y0,     gx, okL, okR);
    float4 h3 = hrow_compute(xp, mp, y0 + 1, gx, okL, okR);
    float4 h4;

    float* orow = op + (size_t)y0 * WW + gx;

#pragma unroll 4
    for (int r = 0; r < ROWS_PER_WARP; ++r) {
        h4 = hrow_compute(xp, mp, y0 + r + 2, gx, okL, okR);

        float4 o;
        o.x = G0 * (h0.x + h4.x) + G1 * (h1.x + h3.x) + G2 * h2.x;
        o.y = G0 * (h0.y + h4.y) + G1 * (h1.y + h3.y) + G2 * h2.y;
        o.z = G0 * (h0.z + h4.z) + G1 * (h1.z + h3.z) + G2 * h2.z;
        o.w = G0 * (h0.w + h4.w) + G1 * (h1.w + h3.w) + G2 * h2.w;

        o.x = fminf(fmaxf(o.x, 0.0f), 1.0f);
        o.y = fminf(fmaxf(o.y, 0.0f), 1.0f);
        o.z = fminf(fmaxf(o.z, 0.0f), 1.0f);
        o.w = fminf(fmaxf(o.w, 0.0f), 1.0f);

        *reinterpret_cast<float4*>(orow) = o;
        orow += WW;

        h0 = h1; h1 = h2; h2 = h3; h3 = h4;
    }
}

// ---------------------------------------------------------------------------
// Launch
// ---------------------------------------------------------------------------
extern "C" void kernel_launch(void* const* d_in, const int* in_sizes, int n_in,
                              void* d_out, int out_size) {
    const float* x  = (const float*)d_in[0];
    const int*   ys = (const int*)d_in[1];
    const int*   xs = (const int*)d_in[2];
    const int*   rs = (const int*)d_in[3];
    float* out = (float*)d_out;

    // 1) zero mask: B*H*W/16 uint4 elements
    {
        int n = (BB * HH * WW) / 16;            // 1,048,576
        zero_mask_kernel<<<n / 256, 256>>>();
    }
    // 2) stamp flakes
    {
        int n = BB * NFLAKES;                   // 251,648
        stamp_kernel<<<(n + 255) / 256, 256>>>(ys, xs, rs);
    }
    // 3) fused substitute + separable blur + clip (register sliding window)
    {
        // grid.x: 1024/128 = 8 column strips
        // grid.y: 1024 / (8 warps * 32 rows) = 4 row blocks
        // grid.z: 48 planes
        dim3 grid(WW / 128, HH / (WARPS_PER_BLOCK * ROWS_PER_WARP), BB * CC);
        blur_kernel<<<grid, 256>>>(x, out);
    }
}